// round 2
// baseline (speedup 1.0000x reference)
#include <cuda_runtime.h>
#include <cfloat>
#include <cstdint>

#define BB 16
#define NN 2048
#define KNB 20

// ---------------- device scratch (allocation-free rule) ----------------
static __device__ float g_xT0 [BB * NN * 4];
static __device__ float g_sq  [BB * NN];
static __device__ float g_feat[BB * NN * 320];
static __device__ int   g_idx [BB * NN * KNB];
static __device__ float g_yT  [BB * NN * 256];
static __device__ float g_W2  [256 * 64];
static __device__ float g_gf  [BB * 1024];
static __device__ float g_fc0 [BB * 512];
static __device__ float g_fc1 [BB * 256];

// ---------------- f32x2 helpers (FFMA2: 2x fp32 FMA throughput) --------
__device__ __forceinline__ void ffma2(unsigned long long &acc,
                                      unsigned long long a,
                                      unsigned long long b) {
    asm("fma.rn.f32x2 %0, %1, %2, %0;" : "+l"(acc) : "l"(a), "l"(b));
}
__device__ __forceinline__ unsigned long long add2(unsigned long long a,
                                                   unsigned long long b) {
    unsigned long long d;
    asm("add.rn.f32x2 %0, %1, %2;" : "=l"(d) : "l"(a), "l"(b));
    return d;
}
__device__ __forceinline__ float hsum2(unsigned long long a) {
    union { unsigned long long u; float2 f; } t; t.u = a;
    return t.f.x + t.f.y;
}

// ---------------- prep: x [B,3,N] -> xT0 [B,N,4] + sq -------------------
__global__ void k_transpose_x0(const float* __restrict__ x,
                               float* __restrict__ xT0,
                               float* __restrict__ sq) {
    int i = blockIdx.x * blockDim.x + threadIdx.x;
    if (i >= BB * NN) return;
    int b = i >> 11, n = i & (NN - 1);
    float v0 = x[(b * 3 + 0) * NN + n];
    float v1 = x[(b * 3 + 1) * NN + n];
    float v2 = x[(b * 3 + 2) * NN + n];
    *reinterpret_cast<float4*>(xT0 + (size_t)i * 4) = make_float4(v0, v1, v2, 0.f);
    sq[i] = v0 * v0 + v1 * v1 + v2 * v2;
}

// ---------- W2 [2F][Cs]: rows 0..F-1 = w_c - w_n ; rows F..2F-1 = w_n ---
__global__ void k_build_w2(const float* __restrict__ w,
                           float* __restrict__ dst, int F, int C, int Cs) {
    int i = blockIdx.x * blockDim.x + threadIdx.x;
    if (i >= 2 * F * Cs) return;
    int f2 = i / Cs, c = i - f2 * Cs;
    float val = 0.f;
    if (c < C) {
        if (f2 < F) val = w[f2 * 2 * C + c] - w[f2 * 2 * C + C + c];
        else        val = w[(f2 - F) * 2 * C + C + c];
    }
    dst[i] = val;
}

// ---------------- kNN: top-20 nearest (excluding self), order-free ------
template <int CS>
__global__ void __launch_bounds__(128) k_knn(const float* __restrict__ xT,
                                             int rowStride,
                                             const float* __restrict__ sq,
                                             int* __restrict__ outidx) {
    constexpr int TROW = CS + 4;
    __shared__ float s_tile[128 * TROW];
    __shared__ float s_sq[128];

    const int b = blockIdx.y;
    const int r = blockIdx.x * 128 + threadIdx.x;

    // own row into packed f32x2 registers
    unsigned long long xr2[CS / 2];
    {
        const ulonglong2* rp = reinterpret_cast<const ulonglong2*>(
            xT + (size_t)(b * NN + r) * rowStride);
        #pragma unroll
        for (int c4 = 0; c4 < CS / 4; c4++) {
            ulonglong2 v = rp[c4];
            xr2[2 * c4] = v.x; xr2[2 * c4 + 1] = v.y;
        }
    }

    float bd[KNB]; int bi[KNB];
    #pragma unroll
    for (int p = 0; p < KNB; p++) { bd[p] = FLT_MAX; bi[p] = 0; }
    float worst = FLT_MAX;

    const int perRow = CS / 4;
    for (int jt = 0; jt < NN; jt += 128) {
        __syncthreads();
        for (int u = threadIdx.x; u < 128 * perRow; u += 128) {
            int jr = u / perRow, c4 = u - jr * perRow;
            *reinterpret_cast<float4*>(&s_tile[jr * TROW + c4 * 4]) =
                *reinterpret_cast<const float4*>(
                    xT + (size_t)(b * NN + jt + jr) * rowStride + c4 * 4);
        }
        s_sq[threadIdx.x] = sq[b * NN + jt + threadIdx.x];
        __syncthreads();

        for (int jj = 0; jj < 128; jj++) {
            const unsigned long long* row =
                reinterpret_cast<const unsigned long long*>(&s_tile[jj * TROW]);
            float dot;
            if constexpr (CS == 4) {
                unsigned long long a0 = 0, a1 = 0;
                ffma2(a0, xr2[0], row[0]);
                ffma2(a1, xr2[1], row[1]);
                dot = hsum2(add2(a0, a1));
            } else {
                unsigned long long a0 = 0, a1 = 0, a2 = 0, a3 = 0;
                #pragma unroll
                for (int c2 = 0; c2 < CS / 2; c2 += 4) {
                    ffma2(a0, xr2[c2],     row[c2]);
                    ffma2(a1, xr2[c2 + 1], row[c2 + 1]);
                    ffma2(a2, xr2[c2 + 2], row[c2 + 2]);
                    ffma2(a3, xr2[c2 + 3], row[c2 + 3]);
                }
                dot = hsum2(add2(add2(a0, a1), add2(a2, a3)));
            }
            float d = fmaf(-2.f, dot, s_sq[jj]);   // +sq_r omitted (row-const)
            int j = jt + jj;
            if (j != r && d < worst) {
                bool done = false;
                #pragma unroll
                for (int p = 0; p < KNB; p++) {
                    bool take = (!done) && (bd[p] == worst);
                    bd[p] = take ? d : bd[p];
                    bi[p] = take ? j : bi[p];
                    done = done || take;
                }
                float w0 = bd[0];
                #pragma unroll
                for (int p = 1; p < KNB; p++) w0 = fmaxf(w0, bd[p]);
                worst = w0;
            }
        }
    }
    int* op = outidx + (size_t)(b * NN + r) * KNB;
    #pragma unroll
    for (int k = 0; k < KNB; k++) op[k] = bi[k];
}

// ---------------- uv GEMM: yT[b][n][f2] = W2[f2,:] . x[:,n] -------------
template <int CS>
__global__ void __launch_bounds__(256) k_uv(const float* __restrict__ xT,
                                            int rowStride,
                                            const float* __restrict__ W2,
                                            float* __restrict__ yT, int F2) {
    constexpr int TROW = CS + 4;
    __shared__ float s_w[64 * TROW];
    __shared__ float s_x[64 * TROW];
    const int b = blockIdx.z, n0 = blockIdx.x * 64, f0 = blockIdx.y * 64;
    const int perRow = CS / 4;

    for (int u = threadIdx.x; u < 64 * perRow; u += 256) {
        int rr = u / perRow, c4 = u - rr * perRow;
        *reinterpret_cast<float4*>(&s_w[rr * TROW + c4 * 4]) =
            *reinterpret_cast<const float4*>(&W2[(size_t)(f0 + rr) * CS + c4 * 4]);
        *reinterpret_cast<float4*>(&s_x[rr * TROW + c4 * 4]) =
            *reinterpret_cast<const float4*>(
                xT + (size_t)(b * NN + n0 + rr) * rowStride + c4 * 4);
    }
    __syncthreads();

    const int nx = threadIdx.x & 15, fy = threadIdx.x >> 4;
    unsigned long long acc[4][4];
    #pragma unroll
    for (int i = 0; i < 4; i++)
        #pragma unroll
        for (int j = 0; j < 4; j++) acc[i][j] = 0ull;

    #pragma unroll
    for (int c4 = 0; c4 < CS / 4; c4++) {
        ulonglong2 wv[4], xv[4];
        #pragma unroll
        for (int i = 0; i < 4; i++)
            wv[i] = *reinterpret_cast<const ulonglong2*>(&s_w[(fy * 4 + i) * TROW + c4 * 4]);
        #pragma unroll
        for (int j = 0; j < 4; j++)
            xv[j] = *reinterpret_cast<const ulonglong2*>(&s_x[(nx + 16 * j) * TROW + c4 * 4]);
        #pragma unroll
        for (int i = 0; i < 4; i++)
            #pragma unroll
            for (int j = 0; j < 4; j++) {
                ffma2(acc[i][j], wv[i].x, xv[j].x);
                ffma2(acc[i][j], wv[i].y, xv[j].y);
            }
    }
    #pragma unroll
    for (int j = 0; j < 4; j++) {
        float4 o;
        o.x = hsum2(acc[0][j]); o.y = hsum2(acc[1][j]);
        o.z = hsum2(acc[2][j]); o.w = hsum2(acc[3][j]);
        int n = n0 + nx + 16 * j;
        *reinterpret_cast<float4*>(&yT[(size_t)(b * NN + n) * F2 + f0 + fy * 4]) = o;
    }
}

// ------ gather-max: out[n][f] = u_f(n) + bias_f + max_k v_f(idx_k) ------
template <int F>
__global__ void __launch_bounds__(128) k_gathermax(const float* __restrict__ yT,
                                                   const int* __restrict__ idxb,
                                                   const float* __restrict__ bias,
                                                   float* __restrict__ outp,
                                                   float* __restrict__ sqout) {
    constexpr int F2 = 2 * F;
    const int warp = threadIdx.x >> 5, lane = threadIdx.x & 31;
    const int p = blockIdx.x * 4 + warp;
    const int b = p >> 11;
    const int* ip = idxb + (size_t)p * KNB;
    int jr[KNB];
    #pragma unroll
    for (int k = 0; k < KNB; k++) jr[k] = ip[k];

    float ss = 0.f;
    if constexpr (F == 64) {
        int c = lane * 2;
        float2 m = make_float2(-FLT_MAX, -FLT_MAX);
        #pragma unroll 5
        for (int k = 0; k < KNB; k++) {
            float2 v = *reinterpret_cast<const float2*>(
                &yT[(size_t)(b * NN + jr[k]) * F2 + F + c]);
            m.x = fmaxf(m.x, v.x); m.y = fmaxf(m.y, v.y);
        }
        float2 u  = *reinterpret_cast<const float2*>(&yT[(size_t)p * F2 + c]);
        float2 bv = *reinterpret_cast<const float2*>(&bias[c]);
        float2 o = make_float2(u.x + bv.x + m.x, u.y + bv.y + m.y);
        *reinterpret_cast<float2*>(&outp[(size_t)p * 320 + c]) = o;
        ss = o.x * o.x + o.y * o.y;
    } else {
        int c = lane * 4;
        float4 m = make_float4(-FLT_MAX, -FLT_MAX, -FLT_MAX, -FLT_MAX);
        #pragma unroll 5
        for (int k = 0; k < KNB; k++) {
            float4 v = *reinterpret_cast<const float4*>(
                &yT[(size_t)(b * NN + jr[k]) * F2 + F + c]);
            m.x = fmaxf(m.x, v.x); m.y = fmaxf(m.y, v.y);
            m.z = fmaxf(m.z, v.z); m.w = fmaxf(m.w, v.w);
        }
        float4 u  = *reinterpret_cast<const float4*>(&yT[(size_t)p * F2 + c]);
        float4 bv = *reinterpret_cast<const float4*>(&bias[c]);
        float4 o = make_float4(u.x + bv.x + m.x, u.y + bv.y + m.y,
                               u.z + bv.z + m.z, u.w + bv.w + m.w);
        *reinterpret_cast<float4*>(&outp[(size_t)p * 320 + c]) = o;
        ss = o.x * o.x + o.y * o.y + o.z * o.z + o.w * o.w;
    }
    if (sqout) {
        #pragma unroll
        for (int o = 16; o > 0; o >>= 1) ss += __shfl_xor_sync(0xffffffffu, ss, o);
        if (lane == 0) sqout[p] = ss;
    }
}

// ------- conv0 (1024x320) fused with max over N + affine + relu ---------
__global__ void __launch_bounds__(256) k_conv0(const float* __restrict__ feat,
                                               const float* __restrict__ w,
                                               const float* __restrict__ bias,
                                               const float* __restrict__ sc,
                                               const float* __restrict__ tr,
                                               float* __restrict__ gout) {
    constexpr int TROW = 68;
    __shared__ float s_w[64 * TROW];
    __shared__ float s_x[64 * TROW];
    const int b = blockIdx.y, f0 = blockIdx.x * 64;
    const int nx = threadIdx.x & 15, fy = threadIdx.x >> 4;
    float rmax[4] = { -FLT_MAX, -FLT_MAX, -FLT_MAX, -FLT_MAX };

    for (int nt = 0; nt < NN; nt += 64) {
        unsigned long long acc[4][4];
        #pragma unroll
        for (int i = 0; i < 4; i++)
            #pragma unroll
            for (int j = 0; j < 4; j++) acc[i][j] = 0ull;

        for (int cc = 0; cc < 320; cc += 64) {
            __syncthreads();
            for (int u = threadIdx.x; u < 64 * 16; u += 256) {
                int rr = u >> 4, c4 = u & 15;
                *reinterpret_cast<float4*>(&s_w[rr * TROW + c4 * 4]) =
                    *reinterpret_cast<const float4*>(&w[(size_t)(f0 + rr) * 320 + cc + c4 * 4]);
                *reinterpret_cast<float4*>(&s_x[rr * TROW + c4 * 4]) =
                    *reinterpret_cast<const float4*>(
                        &feat[(size_t)(b * NN + nt + rr) * 320 + cc + c4 * 4]);
            }
            __syncthreads();
            #pragma unroll
            for (int c4 = 0; c4 < 16; c4++) {
                ulonglong2 wv[4], xv[4];
                #pragma unroll
                for (int i = 0; i < 4; i++)
                    wv[i] = *reinterpret_cast<const ulonglong2*>(&s_w[(fy * 4 + i) * TROW + c4 * 4]);
                #pragma unroll
                for (int j = 0; j < 4; j++)
                    xv[j] = *reinterpret_cast<const ulonglong2*>(&s_x[(nx + 16 * j) * TROW + c4 * 4]);
                #pragma unroll
                for (int i = 0; i < 4; i++)
                    #pragma unroll
                    for (int j = 0; j < 4; j++) {
                        ffma2(acc[i][j], wv[i].x, xv[j].x);
                        ffma2(acc[i][j], wv[i].y, xv[j].y);
                    }
            }
        }
        #pragma unroll
        for (int i = 0; i < 4; i++) {
            float m = rmax[i];
            #pragma unroll
            for (int j = 0; j < 4; j++) m = fmaxf(m, hsum2(acc[i][j]));
            rmax[i] = m;
        }
    }
    #pragma unroll
    for (int i = 0; i < 4; i++) {
        float v = rmax[i];
        #pragma unroll
        for (int o = 8; o > 0; o >>= 1) v = fmaxf(v, __shfl_xor_sync(0xffffffffu, v, o));
        rmax[i] = v;
    }
    if (nx == 0) {
        #pragma unroll
        for (int i = 0; i < 4; i++) {
            int f = f0 + fy * 4 + i;
            float h = (rmax[i] + bias[f]) * sc[f] + tr[f];
            gout[b * 1024 + f] = fmaxf(h, 0.f);
        }
    }
}

// ---------------- FC: out = relu((in.w^T + b)*s + t) --------------------
__global__ void k_fc(const float* __restrict__ in, const float* __restrict__ w,
                     const float* __restrict__ bias, const float* __restrict__ sc,
                     const float* __restrict__ tr, float* __restrict__ out,
                     int Cin, int O) {
    int i = blockIdx.x * blockDim.x + threadIdx.x;
    if (i >= BB * O) return;
    int b = i / O, o = i - b * O;
    const float4* ip = reinterpret_cast<const float4*>(in + (size_t)b * Cin);
    const float4* wp = reinterpret_cast<const float4*>(w + (size_t)o * Cin);
    float acc = 0.f;
    for (int c = 0; c < Cin / 4; c++) {
        float4 a = ip[c], v = wp[c];
        acc += a.x * v.x + a.y * v.y + a.z * v.z + a.w * v.w;
    }
    float h = (acc + bias[o]) * sc[o] + tr[o];
    out[b * O + o] = fmaxf(h, 0.f);
}

// ---------------- host ---------------------------------------------------
extern "C" void kernel_launch(void* const* d_in, const int* in_sizes, int n_in,
                              void* d_out, int out_size) {
    const float* x       = (const float*)d_in[0];
    const float* ec_w[4] = { (const float*)d_in[1], (const float*)d_in[3],
                             (const float*)d_in[5], (const float*)d_in[7] };
    const float* ec_b[4] = { (const float*)d_in[2], (const float*)d_in[4],
                             (const float*)d_in[6], (const float*)d_in[8] };
    const float* c0w = (const float*)d_in[9];
    const float* c0b = (const float*)d_in[10];
    const float* c0s = (const float*)d_in[11];
    const float* c0t = (const float*)d_in[12];

    void* p;
    cudaGetSymbolAddress(&p, g_xT0);  float* xT0  = (float*)p;
    cudaGetSymbolAddress(&p, g_sq);   float* sq   = (float*)p;
    cudaGetSymbolAddress(&p, g_feat); float* feat = (float*)p;
    cudaGetSymbolAddress(&p, g_idx);  int*   idx  = (int*)p;
    cudaGetSymbolAddress(&p, g_yT);   float* yT   = (float*)p;
    cudaGetSymbolAddress(&p, g_W2);   float* W2   = (float*)p;
    cudaGetSymbolAddress(&p, g_gf);   float* gf   = (float*)p;
    cudaGetSymbolAddress(&p, g_fc0);  float* fc0o = (float*)p;
    cudaGetSymbolAddress(&p, g_fc1);  float* fc1o = (float*)p;

    k_transpose_x0<<<128, 256>>>(x, xT0, sq);

    // ---- layer 0 (C=3 padded to 4, F=64) ----
    k_build_w2<<<(2 * 64 * 4 + 255) / 256, 256>>>(ec_w[0], W2, 64, 3, 4);
    k_knn<4><<<dim3(16, 16), 128>>>(xT0, 4, sq, idx);
    k_uv<4><<<dim3(32, 2, 16), 256>>>(xT0, 4, W2, yT, 128);
    k_gathermax<64><<<8192, 128>>>(yT, idx, ec_b[0], feat + 0, sq);

    // ---- layer 1 (C=64, F=64) ----
    k_build_w2<<<(2 * 64 * 64 + 255) / 256, 256>>>(ec_w[1], W2, 64, 64, 64);
    k_knn<64><<<dim3(16, 16), 128>>>(feat + 0, 320, sq, idx);
    k_uv<64><<<dim3(32, 2, 16), 256>>>(feat + 0, 320, W2, yT, 128);
    k_gathermax<64><<<8192, 128>>>(yT, idx, ec_b[1], feat + 64, sq);

    // ---- layer 2 (C=64, F=64) ----
    k_build_w2<<<(2 * 64 * 64 + 255) / 256, 256>>>(ec_w[2], W2, 64, 64, 64);
    k_knn<64><<<dim3(16, 16), 128>>>(feat + 64, 320, sq, idx);
    k_uv<64><<<dim3(32, 2, 16), 256>>>(feat + 64, 320, W2, yT, 128);
    k_gathermax<64><<<8192, 128>>>(yT, idx, ec_b[2], feat + 128, sq);

    // ---- layer 3 (C=64, F=128) ----
    k_build_w2<<<(2 * 128 * 64 + 255) / 256, 256>>>(ec_w[3], W2, 128, 64, 64);
    k_knn<64><<<dim3(16, 16), 128>>>(feat + 128, 320, sq, idx);
    k_uv<64><<<dim3(32, 4, 16), 256>>>(feat + 128, 320, W2, yT, 256);
    k_gathermax<128><<<8192, 128>>>(yT, idx, ec_b[3], feat + 192, nullptr);

    // ---- conv0 + global max ----
    k_conv0<<<dim3(16, 16), 256>>>(feat, c0w, c0b, c0s, c0t, gf);

    // ---- FC head ----
    k_fc<<<32, 256>>>(gf,   (const float*)d_in[13], (const float*)d_in[14],
                      (const float*)d_in[15], (const float*)d_in[16], fc0o, 1024, 512);
    k_fc<<<16, 256>>>(fc0o, (const float*)d_in[17], (const float*)d_in[18],
                      (const float*)d_in[19], (const float*)d_in[20], fc1o, 512, 256);
    k_fc<<<3, 256>>>(fc1o,  (const float*)d_in[21], (const float*)d_in[22],
                      (const float*)d_in[23], (const float*)d_in[24],
                      (float*)d_out, 256, 40);
}

// round 5
// speedup vs baseline: 1.0644x; 1.0644x over previous
#include <cuda_runtime.h>
#include <cuda_fp16.h>
#include <cfloat>
#include <cstdint>

#define BB 16
#define NN 2048
#define KNB 20

// ---------------- device scratch (allocation-free rule) ----------------
static __device__ float   g_xT0 [BB * NN * 4];
static __device__ float   g_sq  [BB * NN];
static __device__ float   g_feat[BB * NN * 320];
static __device__ int     g_idx [BB * NN * KNB];
static __device__ float   g_yT  [BB * NN * 256];
static __device__ float   g_W2  [256 * 64];
static __device__ float   g_gf  [BB * 1024];
static __device__ float   g_fc0 [BB * 512];
static __device__ float   g_fc1 [BB * 256];
static __device__ __half  g_xhi [BB * NN * 64];
static __device__ __half  g_xlo [BB * NN * 64];

// ---------------- helpers ----------------------------------------------
__device__ __forceinline__ uint32_t smem_u32(const void* p) {
    uint32_t a;
    asm("{ .reg .u64 t; cvta.to.shared.u64 t, %1; cvt.u32.u64 %0, t; }"
        : "=r"(a) : "l"(p));
    return a;
}

__device__ __forceinline__ void ldm4(uint32_t* r, uint32_t addr) {
    asm volatile("ldmatrix.sync.aligned.m8n8.x4.shared.b16 {%0,%1,%2,%3}, [%4];"
                 : "=r"(r[0]), "=r"(r[1]), "=r"(r[2]), "=r"(r[3]) : "r"(addr));
}
__device__ __forceinline__ void mma_f16(float* c, const uint32_t* a,
                                        uint32_t b0, uint32_t b1) {
    asm volatile("mma.sync.aligned.m16n8k16.row.col.f32.f16.f16.f32 "
                 "{%0,%1,%2,%3}, {%4,%5,%6,%7}, {%8,%9}, {%0,%1,%2,%3};"
                 : "+f"(c[0]), "+f"(c[1]), "+f"(c[2]), "+f"(c[3])
                 : "r"(a[0]), "r"(a[1]), "r"(a[2]), "r"(a[3]), "r"(b0), "r"(b1));
}

// ---------------- f32x2 helpers (FFMA2) --------------------------------
__device__ __forceinline__ void ffma2(unsigned long long &acc,
                                      unsigned long long a,
                                      unsigned long long b) {
    asm("fma.rn.f32x2 %0, %1, %2, %0;" : "+l"(acc) : "l"(a), "l"(b));
}
__device__ __forceinline__ float hsum2(unsigned long long a) {
    union { unsigned long long u; float2 f; } t; t.u = a;
    return t.f.x + t.f.y;
}

// ---------------- prep: x [B,3,N] -> xT0 [B,N,4] ------------------------
__global__ void k_transpose_x0(const float* __restrict__ x,
                               float* __restrict__ xT0) {
    int i = blockIdx.x * blockDim.x + threadIdx.x;
    if (i >= BB * NN) return;
    int b = i >> 11, n = i & (NN - 1);
    float v0 = x[(b * 3 + 0) * NN + n];
    float v1 = x[(b * 3 + 1) * NN + n];
    float v2 = x[(b * 3 + 2) * NN + n];
    *reinterpret_cast<float4*>(xT0 + (size_t)i * 4) = make_float4(v0, v1, v2, 0.f);
}

// ------- prep: fp32 rows -> split-fp16 (hi+lo) padded to 64 + sq --------
__global__ void k_prep_f16(const float* __restrict__ src, int rs, int C,
                           __half* __restrict__ xhi,
                           __half* __restrict__ xlo,
                           float* __restrict__ sq) {
    int p = blockIdx.x * blockDim.x + threadIdx.x;
    if (p >= BB * NN) return;
    const float* s = src + (size_t)p * rs;
    float ss = 0.f;
    #pragma unroll 8
    for (int c = 0; c < 64; c++) {
        float v = (c < C) ? s[c] : 0.f;
        ss += v * v;
        __half h = __float2half_rn(v);
        float hf = __half2float(h);
        __half l = __float2half_rn(v - hf);
        xhi[(size_t)p * 64 + c] = h;
        xlo[(size_t)p * 64 + c] = l;
    }
    sq[p] = ss;
}

// ---------- W2 [2F][Cs]: rows 0..F-1 = w_c - w_n ; rows F..2F-1 = w_n ---
__global__ void k_build_w2(const float* __restrict__ w,
                           float* __restrict__ dst, int F, int C, int Cs) {
    int i = blockIdx.x * blockDim.x + threadIdx.x;
    if (i >= 2 * F * Cs) return;
    int f2 = i / Cs, c = i - f2 * Cs;
    float val = 0.f;
    if (c < C) {
        if (f2 < F) val = w[f2 * 2 * C + c] - w[f2 * 2 * C + C + c];
        else        val = w[(f2 - F) * 2 * C + C + c];
    }
    dst[i] = val;
}

// -------- kNN via mma.sync fp16 (split hi/lo), top-20 per row -----------
// Block: 128 threads / 4 warps; 128 query rows; j-tiles of 64 columns.
#define PADB 144                       // bytes per padded fp16 row (72 elems)
#define PADD 67                        // floats per padded D row
#define KOFF_AH 0
#define KOFF_AL (KOFF_AH + 128 * PADB)
#define KOFF_BH (KOFF_AL + 128 * PADB)
#define KOFF_BL (KOFF_BH + 64 * PADB)
#define KOFF_D  (KOFF_BL + 64 * PADB)
#define KOFF_SQ (KOFF_D + 128 * PADD * 4)
#define KNN_SMEM (KOFF_SQ + 64 * 4)

__global__ void __launch_bounds__(128) k_knn_mma(
    const __half* __restrict__ xhi,
    const __half* __restrict__ xlo,
    const float* __restrict__ sq,
    int* __restrict__ outidx) {
    extern __shared__ char smem[];
    const uint32_t sb = smem_u32(smem);
    const int tid = threadIdx.x, lane = tid & 31, wid = tid >> 5;
    const int b = blockIdx.y;
    const int r0 = blockIdx.x * 128;
    const int r = r0 + tid;

    // A fill (persistent): 128 rows x 64 ch, hi+lo
    {
        const uint4* ah = reinterpret_cast<const uint4*>(xhi + ((size_t)b * NN + r0) * 64);
        const uint4* al = reinterpret_cast<const uint4*>(xlo + ((size_t)b * NN + r0) * 64);
        #pragma unroll
        for (int it = 0; it < 8; it++) {
            int u = it * 128 + tid;
            int row = u >> 3, c16 = u & 7;
            uint32_t off = row * PADB + c16 * 16;
            *reinterpret_cast<uint4*>(smem + KOFF_AH + off) = ah[u];
            *reinterpret_cast<uint4*>(smem + KOFF_AL + off) = al[u];
        }
    }

    float bd[KNB]; int bi[KNB];
    #pragma unroll
    for (int p = 0; p < KNB; p++) { bd[p] = FLT_MAX; bi[p] = 0; }
    float worst = FLT_MAX;

    // ldmatrix per-lane address offsets (bytes, within a tile)
    const uint32_t aoff = (uint32_t)(lane & 15) * PADB + (uint32_t)(lane >> 4) * 16;
    const uint32_t boff = (uint32_t)((lane & 7) + ((lane >> 3) & 1) * 8) * PADB +
                          (uint32_t)(lane >> 4) * 16;
    float* sD  = reinterpret_cast<float*>(smem + KOFF_D);
    float* sqj = reinterpret_cast<float*>(smem + KOFF_SQ);

    for (int jt = 0; jt < NN; jt += 64) {
        __syncthreads();
        {
            const uint4* bh = reinterpret_cast<const uint4*>(xhi + ((size_t)b * NN + jt) * 64);
            const uint4* bl = reinterpret_cast<const uint4*>(xlo + ((size_t)b * NN + jt) * 64);
            #pragma unroll
            for (int it = 0; it < 4; it++) {
                int u = it * 128 + tid;
                int row = u >> 3, c16 = u & 7;
                uint32_t off = row * PADB + c16 * 16;
                *reinterpret_cast<uint4*>(smem + KOFF_BH + off) = bh[u];
                *reinterpret_cast<uint4*>(smem + KOFF_BL + off) = bl[u];
            }
            if (tid < 64) sqj[tid] = sq[b * NN + jt + tid];
        }
        __syncthreads();

        float C[2][8][4];
        #pragma unroll
        for (int mt = 0; mt < 2; mt++)
            #pragma unroll
            for (int nt = 0; nt < 8; nt++)
                #pragma unroll
                for (int q = 0; q < 4; q++) C[mt][nt][q] = 0.f;

        #pragma unroll
        for (int pr = 0; pr < 3; pr++) {
            const uint32_t abase = sb + (pr == 2 ? KOFF_AL : KOFF_AH);
            const uint32_t bbase = sb + (pr == 1 ? KOFF_BL : KOFF_BH);
            #pragma unroll
            for (int kk = 0; kk < 4; kk++) {
                uint32_t a0[4], a1[4], bbf[4][4];
                ldm4(a0, abase + (wid * 2 + 0) * 16 * PADB + aoff + kk * 32);
                ldm4(a1, abase + (wid * 2 + 1) * 16 * PADB + aoff + kk * 32);
                #pragma unroll
                for (int nt2 = 0; nt2 < 4; nt2++)
                    ldm4(bbf[nt2], bbase + nt2 * 16 * PADB + boff + kk * 32);
                #pragma unroll
                for (int nt2 = 0; nt2 < 4; nt2++) {
                    mma_f16(C[0][2 * nt2 + 0], a0, bbf[nt2][0], bbf[nt2][2]);
                    mma_f16(C[0][2 * nt2 + 1], a0, bbf[nt2][1], bbf[nt2][3]);
                    mma_f16(C[1][2 * nt2 + 0], a1, bbf[nt2][0], bbf[nt2][2]);
                    mma_f16(C[1][2 * nt2 + 1], a1, bbf[nt2][1], bbf[nt2][3]);
                }
            }
        }

        // store D fragments (warp-local region)
        const int rbase = wid * 32 + (lane >> 2);
        const int cbase = (lane & 3) * 2;
        #pragma unroll
        for (int mt = 0; mt < 2; mt++) {
            #pragma unroll
            for (int nt = 0; nt < 8; nt++) {
                int rr = rbase + mt * 16;
                int cc = nt * 8 + cbase;
                sD[rr * PADD + cc]           = C[mt][nt][0];
                sD[rr * PADD + cc + 1]       = C[mt][nt][1];
                sD[(rr + 8) * PADD + cc]     = C[mt][nt][2];
                sD[(rr + 8) * PADD + cc + 1] = C[mt][nt][3];
            }
        }
        __syncwarp();

        // scan own row (thread tid owns D row tid — same warp that wrote it)
        const float* drow = sD + tid * PADD;
        #pragma unroll 8
        for (int c = 0; c < 64; c++) {
            float d = fmaf(-2.f, drow[c], sqj[c]);
            int j = jt + c;
            if (j != r && d < worst) {
                bool done = false;
                #pragma unroll
                for (int p = 0; p < KNB; p++) {
                    bool take = (!done) && (bd[p] == worst);
                    bd[p] = take ? d : bd[p];
                    bi[p] = take ? j : bi[p];
                    done = done || take;
                }
                float w0 = bd[0];
                #pragma unroll
                for (int p = 1; p < KNB; p++) w0 = fmaxf(w0, bd[p]);
                worst = w0;
            }
        }
    }

    int* op = outidx + (size_t)(b * NN + r) * KNB;
    #pragma unroll
    for (int k = 0; k < KNB; k++) op[k] = bi[k];
}

// ---------------- uv GEMM: yT[b][n][f2] = W2[f2,:] . x[:,n] -------------
template <int CS>
__global__ void __launch_bounds__(256) k_uv(const float* __restrict__ xT,
                                            int rowStride,
                                            const float* __restrict__ W2,
                                            float* __restrict__ yT, int F2) {
    constexpr int TROW = CS + 4;
    __shared__ float s_w[64 * TROW];
    __shared__ float s_x[64 * TROW];
    const int b = blockIdx.z, n0 = blockIdx.x * 64, f0 = blockIdx.y * 64;
    const int perRow = CS / 4;

    for (int u = threadIdx.x; u < 64 * perRow; u += 256) {
        int rr = u / perRow, c4 = u - rr * perRow;
        *reinterpret_cast<float4*>(&s_w[rr * TROW + c4 * 4]) =
            *reinterpret_cast<const float4*>(&W2[(size_t)(f0 + rr) * CS + c4 * 4]);
        *reinterpret_cast<float4*>(&s_x[rr * TROW + c4 * 4]) =
            *reinterpret_cast<const float4*>(
                xT + (size_t)(b * NN + n0 + rr) * rowStride + c4 * 4);
    }
    __syncthreads();

    const int nx = threadIdx.x & 15, fy = threadIdx.x >> 4;
    unsigned long long acc[4][4];
    #pragma unroll
    for (int i = 0; i < 4; i++)
        #pragma unroll
        for (int j = 0; j < 4; j++) acc[i][j] = 0ull;

    #pragma unroll
    for (int c4 = 0; c4 < CS / 4; c4++) {
        ulonglong2 wv[4], xv[4];
        #pragma unroll
        for (int i = 0; i < 4; i++)
            wv[i] = *reinterpret_cast<const ulonglong2*>(&s_w[(fy * 4 + i) * TROW + c4 * 4]);
        #pragma unroll
        for (int j = 0; j < 4; j++)
            xv[j] = *reinterpret_cast<const ulonglong2*>(&s_x[(nx + 16 * j) * TROW + c4 * 4]);
        #pragma unroll
        for (int i = 0; i < 4; i++)
            #pragma unroll
            for (int j = 0; j < 4; j++) {
                ffma2(acc[i][j], wv[i].x, xv[j].x);
                ffma2(acc[i][j], wv[i].y, xv[j].y);
            }
    }
    #pragma unroll
    for (int j = 0; j < 4; j++) {
        float4 o;
        o.x = hsum2(acc[0][j]); o.y = hsum2(acc[1][j]);
        o.z = hsum2(acc[2][j]); o.w = hsum2(acc[3][j]);
        int n = n0 + nx + 16 * j;
        *reinterpret_cast<float4*>(&yT[(size_t)(b * NN + n) * F2 + f0 + fy * 4]) = o;
    }
}

// ------ gather-max: out[n][f] = u_f(n) + bias_f + max_k v_f(idx_k) ------
template <int F>
__global__ void __launch_bounds__(128) k_gathermax(const float* __restrict__ yT,
                                                   const int* __restrict__ idxb,
                                                   const float* __restrict__ bias,
                                                   float* __restrict__ outp) {
    constexpr int F2 = 2 * F;
    const int warp = threadIdx.x >> 5, lane = threadIdx.x & 31;
    const int p = blockIdx.x * 4 + warp;
    const int b = p >> 11;
    const int* ip = idxb + (size_t)p * KNB;
    int jr[KNB];
    #pragma unroll
    for (int k = 0; k < KNB; k++) jr[k] = ip[k];

    if constexpr (F == 64) {
        int c = lane * 2;
        float2 m = make_float2(-FLT_MAX, -FLT_MAX);
        #pragma unroll 5
        for (int k = 0; k < KNB; k++) {
            float2 v = *reinterpret_cast<const float2*>(
                &yT[(size_t)(b * NN + jr[k]) * F2 + F + c]);
            m.x = fmaxf(m.x, v.x); m.y = fmaxf(m.y, v.y);
        }
        float2 u  = *reinterpret_cast<const float2*>(&yT[(size_t)p * F2 + c]);
        float2 bv = *reinterpret_cast<const float2*>(&bias[c]);
        *reinterpret_cast<float2*>(&outp[(size_t)p * 320 + c]) =
            make_float2(u.x + bv.x + m.x, u.y + bv.y + m.y);
    } else {
        int c = lane * 4;
        float4 m = make_float4(-FLT_MAX, -FLT_MAX, -FLT_MAX, -FLT_MAX);
        #pragma unroll 5
        for (int k = 0; k < KNB; k++) {
            float4 v = *reinterpret_cast<const float4*>(
                &yT[(size_t)(b * NN + jr[k]) * F2 + F + c]);
            m.x = fmaxf(m.x, v.x); m.y = fmaxf(m.y, v.y);
            m.z = fmaxf(m.z, v.z); m.w = fmaxf(m.w, v.w);
        }
        float4 u  = *reinterpret_cast<const float4*>(&yT[(size_t)p * F2 + c]);
        float4 bv = *reinterpret_cast<const float4*>(&bias[c]);
        *reinterpret_cast<float4*>(&outp[(size_t)p * 320 + c]) =
            make_float4(u.x + bv.x + m.x, u.y + bv.y + m.y,
                        u.z + bv.z + m.z, u.w + bv.w + m.w);
    }
}

// ------- conv0 (1024x320) fused with max over N + affine + relu ---------
__global__ void __launch_bounds__(256) k_conv0(const float* __restrict__ feat,
                                               const float* __restrict__ w,
                                               const float* __restrict__ bias,
                                               const float* __restrict__ sc,
                                               const float* __restrict__ tr,
                                               float* __restrict__ gout) {
    constexpr int TROW = 68;
    __shared__ float s_w[64 * TROW];
    __shared__ float s_x[64 * TROW];
    const int b = blockIdx.y, f0 = blockIdx.x * 64;
    const int nx = threadIdx.x & 15, fy = threadIdx.x >> 4;
    float rmax[4] = { -FLT_MAX, -FLT_MAX, -FLT_MAX, -FLT_MAX };

    for (int nt = 0; nt < NN; nt += 64) {
        unsigned long long acc[4][4];
        #pragma unroll
        for (int i = 0; i < 4; i++)
            #pragma unroll
            for (int j = 0; j < 4; j++) acc[i][j] = 0ull;

        for (int cc = 0; cc < 320; cc += 64) {
            __syncthreads();
            for (int u = threadIdx.x; u < 64 * 16; u += 256) {
                int rr = u >> 4, c4 = u & 15;
                *reinterpret_cast<float4*>(&s_w[rr * TROW + c4 * 4]) =
                    *reinterpret_cast<const float4*>(&w[(size_t)(f0 + rr) * 320 + cc + c4 * 4]);
                *reinterpret_cast<float4*>(&s_x[rr * TROW + c4 * 4]) =
                    *reinterpret_cast<const float4*>(
                        &feat[(size_t)(b * NN + nt + rr) * 320 + cc + c4 * 4]);
            }
            __syncthreads();
            #pragma unroll
            for (int c4 = 0; c4 < 16; c4++) {
                ulonglong2 wv[4], xv[4];
                #pragma unroll
                for (int i = 0; i < 4; i++)
                    wv[i] = *reinterpret_cast<const ulonglong2*>(&s_w[(fy * 4 + i) * TROW + c4 * 4]);
                #pragma unroll
                for (int j = 0; j < 4; j++)
                    xv[j] = *reinterpret_cast<const ulonglong2*>(&s_x[(nx + 16 * j) * TROW + c4 * 4]);
                #pragma unroll
                for (int i = 0; i < 4; i++)
                    #pragma unroll
                    for (int j = 0; j < 4; j++) {
                        ffma2(acc[i][j], wv[i].x, xv[j].x);
                        ffma2(acc[i][j], wv[i].y, xv[j].y);
                    }
            }
        }
        #pragma unroll
        for (int i = 0; i < 4; i++) {
            float m = rmax[i];
            #pragma unroll
            for (int j = 0; j < 4; j++) m = fmaxf(m, hsum2(acc[i][j]));
            rmax[i] = m;
        }
    }
    #pragma unroll
    for (int i = 0; i < 4; i++) {
        float v = rmax[i];
        #pragma unroll
        for (int o = 8; o > 0; o >>= 1) v = fmaxf(v, __shfl_xor_sync(0xffffffffu, v, o));
        rmax[i] = v;
    }
    if (nx == 0) {
        #pragma unroll
        for (int i = 0; i < 4; i++) {
            int f = f0 + fy * 4 + i;
            float h = (rmax[i] + bias[f]) * sc[f] + tr[f];
            gout[b * 1024 + f] = fmaxf(h, 0.f);
        }
    }
}

// ---------------- FC: out = relu((in.w^T + b)*s + t) --------------------
__global__ void k_fc(const float* __restrict__ in, const float* __restrict__ w,
                     const float* __restrict__ bias, const float* __restrict__ sc,
                     const float* __restrict__ tr, float* __restrict__ out,
                     int Cin, int O) {
    int i = blockIdx.x * blockDim.x + threadIdx.x;
    if (i >= BB * O) return;
    int b = i / O, o = i - b * O;
    const float4* ip = reinterpret_cast<const float4*>(in + (size_t)b * Cin);
    const float4* wp = reinterpret_cast<const float4*>(w + (size_t)o * Cin);
    float acc = 0.f;
    for (int c = 0; c < Cin / 4; c++) {
        float4 a = ip[c], v = wp[c];
        acc += a.x * v.x + a.y * v.y + a.z * v.z + a.w * v.w;
    }
    float h = (acc + bias[o]) * sc[o] + tr[o];
    out[b * O + o] = fmaxf(h, 0.f);
}

// ---------------- host ---------------------------------------------------
extern "C" void kernel_launch(void* const* d_in, const int* in_sizes, int n_in,
                              void* d_out, int out_size) {
    const float* x       = (const float*)d_in[0];
    const float* ec_w[4] = { (const float*)d_in[1], (const float*)d_in[3],
                             (const float*)d_in[5], (const float*)d_in[7] };
    const float* ec_b[4] = { (const float*)d_in[2], (const float*)d_in[4],
                             (const float*)d_in[6], (const float*)d_in[8] };
    const float* c0w = (const float*)d_in[9];
    const float* c0b = (const float*)d_in[10];
    const float* c0s = (const float*)d_in[11];
    const float* c0t = (const float*)d_in[12];

    void* p;
    cudaGetSymbolAddress(&p, g_xT0);  float* xT0  = (float*)p;
    cudaGetSymbolAddress(&p, g_sq);   float* sq   = (float*)p;
    cudaGetSymbolAddress(&p, g_feat); float* feat = (float*)p;
    cudaGetSymbolAddress(&p, g_idx);  int*   idx  = (int*)p;
    cudaGetSymbolAddress(&p, g_yT);   float* yT   = (float*)p;
    cudaGetSymbolAddress(&p, g_W2);   float* W2   = (float*)p;
    cudaGetSymbolAddress(&p, g_gf);   float* gf   = (float*)p;
    cudaGetSymbolAddress(&p, g_fc0);  float* fc0o = (float*)p;
    cudaGetSymbolAddress(&p, g_fc1);  float* fc1o = (float*)p;
    cudaGetSymbolAddress(&p, g_xhi);  __half* xhi = (__half*)p;
    cudaGetSymbolAddress(&p, g_xlo);  __half* xlo = (__half*)p;

    static bool attr_done = false;
    if (!attr_done) {
        cudaFuncSetAttribute(k_knn_mma, cudaFuncAttributeMaxDynamicSharedMemorySize,
                             KNN_SMEM);
        attr_done = true;
    }

    k_transpose_x0<<<128, 256>>>(x, xT0);
    k_build_w2<<<(2 * 64 * 4 + 255) / 256, 256>>>(ec_w[0], W2, 64, 3, 4);
    k_prep_f16<<<128, 256>>>(xT0, 4, 3, xhi, xlo, sq);
    k_knn_mma<<<dim3(16, 16), 128, KNN_SMEM>>>(xhi, xlo, sq, idx);
    k_uv<4><<<dim3(32, 2, 16), 256>>>(xT0, 4, W2, yT, 128);
    k_gathermax<64><<<8192, 128>>>(yT, idx, ec_b[0], feat + 0);

    // ---- layer 1 (C=64, F=64) ----
    k_build_w2<<<(2 * 64 * 64 + 255) / 256, 256>>>(ec_w[1], W2, 64, 64, 64);
    k_prep_f16<<<128, 256>>>(feat + 0, 320, 64, xhi, xlo, sq);
    k_knn_mma<<<dim3(16, 16), 128, KNN_SMEM>>>(xhi, xlo, sq, idx);
    k_uv<64><<<dim3(32, 2, 16), 256>>>(feat + 0, 320, W2, yT, 128);
    k_gathermax<64><<<8192, 128>>>(yT, idx, ec_b[1], feat + 64);

    // ---- layer 2 (C=64, F=64) ----
    k_build_w2<<<(2 * 64 * 64 + 255) / 256, 256>>>(ec_w[2], W2, 64, 64, 64);
    k_prep_f16<<<128, 256>>>(feat + 64, 320, 64, xhi, xlo, sq);
    k_knn_mma<<<dim3(16, 16), 128, KNN_SMEM>>>(xhi, xlo, sq, idx);
    k_uv<64><<<dim3(32, 2, 16), 256>>>(feat + 64, 320, W2, yT, 128);
    k_gathermax<64><<<8192, 128>>>(yT, idx, ec_b[2], feat + 128);

    // ---- layer 3 (C=64, F=128) ----
    k_build_w2<<<(2 * 128 * 64 + 255) / 256, 256>>>(ec_w[3], W2, 128, 64, 64);
    k_prep_f16<<<128, 256>>>(feat + 128, 320, 64, xhi, xlo, sq);
    k_knn_mma<<<dim3(16, 16), 128, KNN_SMEM>>>(xhi, xlo, sq, idx);
    k_uv<64><<<dim3(32, 4, 16), 256>>>(feat + 128, 320, W2, yT, 256);
    k_gathermax<128><<<8192, 128>>>(yT, idx, ec_b[3], feat + 192);

    // ---- conv0 + global max ----
    k_conv0<<<dim3(16, 16), 256>>>(feat, c0w, c0b, c0s, c0t, gf);

    // ---- FC head ----
    k_fc<<<32, 256>>>(gf,   (const float*)d_in[13], (const float*)d_in[14],
                      (const float*)d_in[15], (const float*)d_in[16], fc0o, 1024, 512);
    k_fc<<<16, 256>>>(fc0o, (const float*)d_in[17], (const float*)d_in[18],
                      (const float*)d_in[19], (const float*)d_in[20], fc1o, 512, 256);
    k_fc<<<3, 256>>>(fc1o,  (const float*)d_in[21], (const float*)d_in[22],
                      (const float*)d_in[23], (const float*)d_in[24],
                      (float*)d_out, 256, 40);
}